// round 5
// baseline (speedup 1.0000x reference)
#include <cuda_runtime.h>
#include <cuda_bf16.h>
#include <cstdint>

// Problem constants (match reference)
#define N_B   16
#define T_DIM 4096
#define F_DIM 256
#define PAD_MAX 1228                   // int(0.3 * 4096)
#define TP    (T_DIM + 2 * PAD_MAX)    // 6552

#define OUT_ELEMS (N_B * TP * F_DIM)   // 26,836,992

#define ROWS_PER_WARP  4
#define WARPS_PER_BLK  8
#define ROWS_PER_BLK   (ROWS_PER_WARP * WARPS_PER_BLK)       // 32
#define BLOCKS_PER_N   ((TP + ROWS_PER_BLK - 1) / ROWS_PER_BLK)  // 205

__global__ __launch_bounds__(256)
void random_shift_kernel(const float* __restrict__ in_,
                         const int*   __restrict__ in_lens,
                         const int*   __restrict__ pad,
                         float* __restrict__ out,
                         int tail_count)
{
    const int n    = blockIdx.y;
    const int w    = threadIdx.x >> 5;
    const int lane = threadIdx.x & 31;

    // warp-uniform metadata (L1 broadcast hits)
    const int lens = __ldg(&in_lens[n]);
    const int p0   = __ldg(&pad[n]);
    const int p1   = __ldg(&pad[N_B + n]);
    const int out_len = lens + p0 + p1;

    const float* in_n  = in_ + (size_t)n * T_DIM * F_DIM;
    float*       out_n = out + (size_t)n * TP * F_DIM;

    const int t0 = blockIdx.x * ROWS_PER_BLK + w * ROWS_PER_WARP;

    // Phase 1: per-row uniform source computation
    const float4* sp[ROWS_PER_WARP];
    bool vld[ROWS_PER_WARP];
    bool inb[ROWS_PER_WARP];
    #pragma unroll
    for (int r = 0; r < ROWS_PER_WARP; r++) {
        int t = t0 + r;
        int src;
        if (t < p0)              src = p0 - t;                // left reflect
        else if (t < p0 + lens)  src = t - p0;                 // middle
        else                     src = 2 * lens + p0 - t - 2;  // right reflect
        src = min(max(src, 0), T_DIM - 1);
        inb[r] = (t < TP);
        vld[r] = (t < out_len);
        sp[r]  = reinterpret_cast<const float4*>(in_n + (size_t)src * F_DIM) + lane;
    }

    // Phase 2: 8 independent 16B loads per thread (MLP = 8)
    float4 val[ROWS_PER_WARP][2];
    #pragma unroll
    for (int r = 0; r < ROWS_PER_WARP; r++) {
        #pragma unroll
        for (int h = 0; h < 2; h++) {
            val[r][h] = vld[r] ? __ldg(sp[r] + h * 32)
                               : make_float4(0.f, 0.f, 0.f, 0.f);
        }
    }

    // Phase 3: normal stores — output stays L2-resident across graph replays
    #pragma unroll
    for (int r = 0; r < ROWS_PER_WARP; r++) {
        int t = t0 + r;
        if (inb[r]) {
            float4* op = reinterpret_cast<float4*>(out_n + (size_t)t * F_DIM) + lane;
            #pragma unroll
            for (int h = 0; h < 2; h++) {
                op[h * 32] = val[r][h];
            }
        }
    }

    // Fold out_lens tail write into the first block (values exact in fp32).
    if (blockIdx.x == 0 && blockIdx.y == 0 && threadIdx.x < 16) {
        int ix = threadIdx.x;
        if (ix < tail_count) {
            int ol = __ldg(&in_lens[ix]) + __ldg(&pad[ix]) + __ldg(&pad[N_B + ix]);
            out[OUT_ELEMS + ix] = (float)ol;
        }
    }
}

extern "C" void kernel_launch(void* const* d_in, const int* in_sizes, int n_in,
                              void* d_out, int out_size)
{
    const float* in_  = (const float*)d_in[0];
    const int*   lens = (const int*)d_in[1];
    const int*   pad  = (const int*)d_in[2];
    float*       out  = (float*)d_out;

    int tail = out_size - OUT_ELEMS;   // out_lens packed after main tensor (if present)
    if (tail < 0) tail = 0;

    dim3 grid(BLOCKS_PER_N, N_B, 1);   // 205 x 16 = 3280 blocks
    random_shift_kernel<<<grid, 256>>>(in_, lens, pad, out, tail);
}